// round 16
// baseline (speedup 1.0000x reference)
#include <cuda_runtime.h>
#include <cfloat>

#define MAXB 64
#define MAXG 64
#define MAXBP (64*24576)
#define K3ROWS 96
#define K3THREADS 256

__device__ float d_bto[MAXBP];                 // best_truth_overlap per (b,p)
__device__ int   d_bti[MAXBP];                 // best_truth_idx per (b,p)
__device__ unsigned d_key[MAXBP];              // radix key: pos?0:ce_bits
__device__ unsigned long long d_bestkey[MAXB*MAXG];  // packed (iou_bits<<32 | ~p)
__device__ int d_poscnt[MAXB];
__device__ double d_loss_l;
__device__ double d_cepos;
__device__ double d_ceneg;

__global__ void k0a_init(int BG){
  int t = blockIdx.x*blockDim.x + threadIdx.x;
  if (t < BG) d_bestkey[t] = 0ULL;
}
__global__ void k0b_init(int B){
  int t = blockIdx.x*blockDim.x + threadIdx.x;
  if (t < B) d_poscnt[t] = 0;
}
__global__ void k0c_init(){
  if (threadIdx.x == 0){ d_loss_l = 0.0; d_cepos = 0.0; d_ceneg = 0.0; }
}

// Fused matcher: each IoU computed ONCE. Per-p argmax over g (strict > ==
// first-index) in registers; per-g argmax over p via warp __reduce_max_sync
// + lowest-lane tie-break, merged through shared then global atomicMax.
__global__ void __launch_bounds__(256)
k1_match(const float* __restrict__ dbox,
         const float* __restrict__ targ,
         int P, int G){
  __shared__ float4 sgt[MAXG];
  __shared__ float  sarea[MAXG];
  __shared__ unsigned long long skey[MAXG];
  const int b = blockIdx.y;
  const int tid = threadIdx.x;
  if (tid < G){
    const float* t = targ + ((long long)b*G + tid)*5;
    float x1=t[0], y1=t[1], x2=t[2], y2=t[3];
    sgt[tid] = make_float4(x1,y1,x2,y2);
    sarea[tid] = (x2-x1)*(y2-y1);
    skey[tid] = 0ULL;
  }
  __syncthreads();
  const int p = blockIdx.x*blockDim.x + tid;
  const int pc = min(p, P-1);                  // dummy lanes clone last prior
  float4 pr = reinterpret_cast<const float4*>(dbox)[pc];
  float px1 = pr.x - pr.z*0.5f, py1 = pr.y - pr.w*0.5f;
  float px2 = pr.x + pr.z*0.5f, py2 = pr.y + pr.w*0.5f;
  float pa = (px2-px1)*(py2-py1);
  float bestv = -1.0f; int besti = 0;
  const int lane = tid & 31;
  const int warp_base_p = blockIdx.x*blockDim.x + (tid & ~31);
  for (int g = 0; g < G; ++g){
    float4 t = sgt[g];
    float iw = fmaxf(fminf(t.z,px2) - fmaxf(t.x,px1), 0.0f);
    float ih = fmaxf(fminf(t.w,py2) - fmaxf(t.y,py1), 0.0f);
    float inter = iw*ih;
    float iou = __fdividef(inter, sarea[g] + pa - inter);
    if (iou > bestv){ bestv = iou; besti = g; }
    unsigned ib = __float_as_uint(iou);          // iou >= 0 -> bits monotone
    unsigned wmax = __reduce_max_sync(0xffffffffu, ib);
    unsigned bal = __ballot_sync(0xffffffffu, ib == wmax);
    if (lane == 0){
      int src = __ffs(bal) - 1;                  // lowest lane = lowest p
      unsigned pbest = (unsigned)(warp_base_p + src);
      unsigned long long key = ((unsigned long long)wmax << 32)
                             | (unsigned long long)(0xFFFFFFFFu - pbest);
      if (key > skey[g]) atomicMax(&skey[g], key);
    }
  }
  if (p < P){
    long long o = (long long)b*P + p;
    d_bto[o] = bestv;
    d_bti[o] = besti;
  }
  __syncthreads();
  if (tid < G && skey[tid] > 0ULL) atomicMax(&d_bestkey[b*G + tid], skey[tid]);
}

__device__ __forceinline__ float sl1(float d){
  d = fabsf(d);
  return d < 1.0f ? 0.5f*d*d : d - 0.5f;
}

// Half-row per thread over a 96-row smem tile staged via cp.async.cg.
// Force-override via per-block smem table (atomicMax g, max-g == last-wins)
// instead of a per-row G-scan: removes ~50M compare-iterations chip-wide.
__global__ void __launch_bounds__(K3THREADS)
k3_ce(const float* __restrict__ conf,
      const float* __restrict__ loc,
      const float* __restrict__ dbox,
      const float* __restrict__ targ,
      int P, int G, int C){
  __shared__ float srow[K3ROWS*81];
  __shared__ int sforce[K3ROWS];     // forced g per row, -1 = none
  __shared__ double s_ll, s_ce;
  __shared__ int s_np;
  const int tid = threadIdx.x;
  const int b = blockIdx.y;
  const int p0 = blockIdx.x * K3ROWS;
  const int rows = min(K3ROWS, P - p0);
  if (tid == 0){ s_ll = 0.0; s_ce = 0.0; s_np = 0; }
  if (tid < K3ROWS) sforce[tid] = -1;
  unsigned fp = 0xFFFFFFFFu;
  if (tid < G)
    fp = 0xFFFFFFFFu - (unsigned)(d_bestkey[b*G + tid] & 0xFFFFFFFFull);
  __syncthreads();
  if (tid < G && fp >= (unsigned)p0 && fp < (unsigned)(p0 + rows))
    atomicMax(&sforce[fp - p0], tid);
  const int elems = rows * 81;
  const float* src = conf + ((long long)b*P + p0)*81;
  const int nf4 = elems >> 2;
  {
    const float4* s4 = (const float4*)src;
    unsigned sbase = (unsigned)__cvta_generic_to_shared(srow);
    #pragma unroll
    for (int u = 0; u < 8; ++u){
      int i = tid + u*K3THREADS;
      if (i < nf4)
        asm volatile("cp.async.cg.shared.global [%0], [%1], 16;"
                     :: "r"(sbase + i*16), "l"(s4 + i) : "memory");
    }
    asm volatile("cp.async.commit_group;" ::: "memory");
    for (int i = (nf4<<2) + tid; i < elems; i += K3THREADS) srow[i] = src[i];
    asm volatile("cp.async.wait_group 0;" ::: "memory");
  }
  __syncthreads();
  const int r = tid >> 1, half = tid & 1;
  float acc = 0.0f;
  if (r < rows){
    const int cbase = r*81 + half*40;
    float a0 = 0.f, a1 = 0.f, a2 = 0.f, a3 = 0.f;
    #pragma unroll
    for (int c = 0; c < 40; c += 4){
      a0 += __expf(srow[cbase + c]);
      a1 += __expf(srow[cbase + c + 1]);
      a2 += __expf(srow[cbase + c + 2]);
      a3 += __expf(srow[cbase + c + 3]);
    }
    acc = (a0 + a1) + (a2 + a3);
    if (half) acc += __expf(srow[r*81 + 80]);
  }
  float sum = acc + __shfl_xor_sync(0xffffffffu, acc, 1);
  if (half == 0 && r < rows){
    const int p = p0 + r;
    const long long o = (long long)b*P + p;
    float bto = d_bto[o];
    int bti = d_bti[o];
    int fg = sforce[r];
    if (fg >= 0){ bto = 2.0f; bti = fg; }
    bool pos = bto >= 0.5f;
    const float* tb = targ + ((long long)b*G + bti)*5;
    int ct = 0;
    if (pos) ct = (int)tb[4] + 1;
    float ce = __logf(sum) - srow[r*81 + ct];
    d_key[o] = pos ? 0u : __float_as_uint(ce);
    if (pos){
      float x1=tb[0], y1=tb[1], x2=tb[2], y2=tb[3];
      float4 pr = reinterpret_cast<const float4*>(dbox)[p];
      float gcx = ((x1+x2)*0.5f - pr.x) / (0.1f*pr.z);
      float gcy = ((y1+y2)*0.5f - pr.y) / (0.1f*pr.w);
      float gw = logf((x2-x1)/pr.z) / 0.2f;
      float gh = logf((y2-y1)/pr.w) / 0.2f;
      float4 lr = reinterpret_cast<const float4*>(loc)[(long long)b*P + p];
      float ll = sl1(lr.x-gcx) + sl1(lr.y-gcy) + sl1(lr.z-gw) + sl1(lr.w-gh);
      atomicAdd(&s_ll, (double)ll);
      atomicAdd(&s_ce, (double)ce);
      atomicAdd(&s_np, 1);
    }
  }
  __syncthreads();
  if (tid == 0 && s_np > 0){
    atomicAdd(&d_loss_l, s_ll);
    atomicAdd(&d_cepos, s_ce);
    atomicAdd(&d_poscnt[b], s_np);
  }
}

// Per-batch radix select: keys in dynamic smem; suffix scan done entirely in
// warp 0 (8 bins/lane + shfl suffix-scan) -> ~5 barriers/pass instead of 19.
extern __shared__ unsigned skeys[];
__global__ void __launch_bounds__(1024, 1)
k4_select(int P){
  const int b = blockIdx.x;
  const int tid = threadIdx.x;
  const int bs = 1024;
  __shared__ int hist[8*257];
  __shared__ int suf[257];
  __shared__ unsigned s_prefix;
  __shared__ int s_krem;
  __shared__ double sred[32];
  __shared__ int sredi[32];
  const long long base = (long long)b*P;
  #pragma unroll 8
  for (int p = tid; p < P; p += bs) skeys[p] = d_key[base + p];
  const int k = min(3*d_poscnt[b], P);
  const int copy = tid & 7;
  __syncthreads();
  unsigned prefix = 0;
  int krem = k;
  for (int byte = 3; byte >= 0; --byte){
    for (int i = tid; i < 8*257; i += bs) hist[i] = 0;
    __syncthreads();
    unsigned mhigh = (byte == 3) ? 0u : (0xFFFFFFFFu << ((byte+1)*8));
    for (int p = tid; p < P; p += bs){
      unsigned key = skeys[p];
      if ((key & mhigh) == (prefix & mhigh))
        atomicAdd(&hist[copy*257 + ((key >> (byte*8)) & 255)], 1);
    }
    __syncthreads();
    if (tid < 32){
      int v[8], loc_suf[8];
      #pragma unroll
      for (int j = 0; j < 8; ++j){
        int bin = tid*8 + j;
        int tot = 0;
        #pragma unroll
        for (int c = 0; c < 8; ++c) tot += hist[c*257 + bin];
        v[j] = tot;
      }
      int run = 0;
      #pragma unroll
      for (int j = 7; j >= 0; --j){ run += v[j]; loc_suf[j] = run; }
      int acc = run;  // lane total
      #pragma unroll
      for (int off = 1; off < 32; off <<= 1){
        int t = __shfl_down_sync(0xffffffffu, acc, off);
        if (tid + off < 32) acc += t;
      }
      int above_lane = acc - run;   // sum over lanes > tid
      #pragma unroll
      for (int j = 0; j < 8; ++j) suf[tid*8 + j] = above_lane + loc_suf[j];
      if (tid == 0) suf[256] = 0;
    }
    __syncthreads();
    if (krem == 0){
      if (tid == 0){ s_prefix = 0xFFFFFFFFu; s_krem = 0; }
    } else if (tid < 256){
      int here = suf[tid], above = suf[tid + 1];
      if (here >= krem && above < krem){
        s_prefix = prefix | ((unsigned)tid << (byte*8));
        s_krem = krem - above;
      }
    }
    __syncthreads();
    prefix = s_prefix; krem = s_krem;
    __syncthreads();
  }
  const unsigned T = prefix;   // exact bits of the k-th largest key
  double s = 0.0; int cnt = 0;
  for (int p = tid; p < P; p += bs){
    unsigned key = skeys[p];
    if (key > T){ s += (double)__uint_as_float(key); cnt++; }
  }
  #pragma unroll
  for (int o = 16; o > 0; o >>= 1){
    s += __shfl_xor_sync(0xffffffffu, s, o);
    cnt += __shfl_xor_sync(0xffffffffu, cnt, o);
  }
  if ((tid & 31) == 0){ sred[tid>>5] = s; sredi[tid>>5] = cnt; }
  __syncthreads();
  if (tid == 0){
    double tot = 0.0; int c = 0;
    for (int w = 0; w < bs/32; ++w){ tot += sred[w]; c += sredi[w]; }
    int rem = k - c;
    if (rem > 0) tot += (double)rem * (double)__uint_as_float(T);
    atomicAdd(&d_ceneg, tot);
  }
}

__global__ void k5_final(float* out, int B, int outn){
  if (threadIdx.x == 0){
    long long N = 0;
    for (int b = 0; b < B; ++b) N += d_poscnt[b];
    double Nd = (double)N;
    out[0] = (float)((d_cepos + d_ceneg) / Nd);
    if (outn > 1) out[1] = (float)(d_loss_l / Nd);
  }
}

extern "C" void kernel_launch(void* const* d_in, const int* in_sizes, int n_in,
                              void* d_out, int out_size){
  const float* loc  = (const float*)d_in[0];
  const float* conf = (const float*)d_in[1];
  const float* dbox = (const float*)d_in[2];
  const float* targ = (const float*)d_in[3];
  const int P = in_sizes[2] / 4;
  const int B = in_sizes[0] / (P * 4);
  const int C = (int)((long long)in_sizes[1] / ((long long)B * P));
  const int G = in_sizes[3] / (B * 5);

  const size_t k4smem = (size_t)P * sizeof(unsigned);
  cudaFuncSetAttribute(k4_select, cudaFuncAttributeMaxDynamicSharedMemorySize,
                       (int)k4smem);

  k0a_init<<<(B*G + 255)/256, 256>>>(B*G);                  // idx 0
  k0b_init<<<1, 256>>>(B);                                  // idx 1
  k0c_init<<<1, 32>>>();                                    // idx 2

  dim3 g1((P + 255)/256, B);
  k1_match<<<g1, 256>>>(dbox, targ, P, G);                  // idx 3 (profiled)

  dim3 g3((P + K3ROWS - 1)/K3ROWS, B);
  k3_ce<<<g3, K3THREADS>>>(conf, loc, dbox, targ, P, G, C); // idx 4

  k4_select<<<B, 1024, k4smem>>>(P);                        // idx 5

  k5_final<<<1, 32>>>((float*)d_out, B, out_size);          // idx 6
}